// round 1
// baseline (speedup 1.0000x reference)
#include <cuda_runtime.h>

// LightGCN: out = sum_i a_i * A^i X W + b  ==  sum_i a_i * A^i (X W) + b
// Propagate in the 2-dim projected space instead of 128-dim embedding space.

#define N_NODES 100000
#define N_EDGES 1600000
#define DIM     128
#define NLAYERS 3

// Scratch (allocation-free): device globals, 16B-aligned for vector loads.
__device__ __align__(16) float g_a[NLAYERS + 1];
__device__ __align__(16) float g_bufA[2 * N_NODES];
__device__ __align__(16) float g_bufB[2 * N_NODES];
__device__ __align__(16) float g_acc [2 * N_NODES];

__device__ __forceinline__ const float* cur_of(int p) { return p ? g_bufB : g_bufA; }
__device__ __forceinline__ float*       nxt_of(int p) { return p ? g_bufA : g_bufB; }

// ---------------------------------------------------------------------------
// softmax over alpha[4] -> g_a
__global__ void k_softmax(const float* __restrict__ alpha) {
    float m = alpha[0];
    #pragma unroll
    for (int i = 1; i < NLAYERS + 1; i++) m = fmaxf(m, alpha[i]);
    float e[NLAYERS + 1], s = 0.f;
    #pragma unroll
    for (int i = 0; i < NLAYERS + 1; i++) { e[i] = expf(alpha[i] - m); s += e[i]; }
    #pragma unroll
    for (int i = 0; i < NLAYERS + 1; i++) g_a[i] = e[i] / s;
}

// ---------------------------------------------------------------------------
// Y = X W (X = embedding[node_indices]); cur = Y; acc = a0 * Y.
// One warp per node: lane l loads float4 at feature 4l (512B coalesced/warp),
// dots against W[128][2], warp-reduces.
__global__ void k_init(const int* __restrict__ node_idx,
                       const float* __restrict__ emb,
                       const float* __restrict__ W) {
    int warp = (blockIdx.x * blockDim.x + threadIdx.x) >> 5;
    int lane = threadIdx.x & 31;
    if (warp >= N_NODES) return;

    int src = node_idx[warp];
    float4 v = reinterpret_cast<const float4*>(emb + (long long)src * DIM)[lane];
    // W rows k = 4*lane .. 4*lane+3, layout [k][c] interleaved.
    const float4* w4 = reinterpret_cast<const float4*>(W + lane * 8);
    float4 w01 = w4[0];   // k0c0 k0c1 k1c0 k1c1
    float4 w23 = w4[1];   // k2c0 k2c1 k3c0 k3c1

    float s0 = v.x * w01.x + v.y * w01.z + v.z * w23.x + v.w * w23.z;
    float s1 = v.x * w01.y + v.y * w01.w + v.z * w23.y + v.w * w23.w;
    #pragma unroll
    for (int o = 16; o; o >>= 1) {
        s0 += __shfl_xor_sync(0xFFFFFFFFu, s0, o);
        s1 += __shfl_xor_sync(0xFFFFFFFFu, s1, o);
    }
    if (lane == 0) {
        float a0 = g_a[0];
        g_bufA[2 * warp + 0] = s0;
        g_bufA[2 * warp + 1] = s1;
        g_acc [2 * warp + 0] = a0 * s0;
        g_acc [2 * warp + 1] = a0 * s1;
    }
}

// ---------------------------------------------------------------------------
// zero the nxt buffer for this layer
__global__ void k_zero(int parity) {
    int i = blockIdx.x * blockDim.x + threadIdx.x;
    if (i < 2 * N_NODES) nxt_of(parity)[i] = 0.f;
}

// ---------------------------------------------------------------------------
// edge-parallel SpMM in 2-dim space: nxt[r] += val * cur[c]
__global__ void k_scatter(const int* __restrict__ row,
                          const int* __restrict__ col,
                          const float* __restrict__ val,
                          int parity) {
    int e = blockIdx.x * blockDim.x + threadIdx.x;
    if (e >= N_EDGES) return;
    int r = row[e];
    int c = col[e];
    float v = val[e];
    const float* cur = cur_of(parity);
    float*       nxt = nxt_of(parity);
    float2 x = reinterpret_cast<const float2*>(cur)[c];
    atomicAdd(nxt + 2 * r + 0, v * x.x);   // result unused -> RED
    atomicAdd(nxt + 2 * r + 1, v * x.y);
}

// ---------------------------------------------------------------------------
// acc += a[layer+1] * nxt   (layers 0,1)
__global__ void k_accum(int layer, int parity) {
    int i = blockIdx.x * blockDim.x + threadIdx.x;
    if (i >= 2 * N_NODES) return;
    g_acc[i] += g_a[layer + 1] * nxt_of(parity)[i];
}

// ---------------------------------------------------------------------------
// out = acc + a[3] * nxt + b   (fused last-layer accumulate + bias)
__global__ void k_final(const float* __restrict__ b, float* __restrict__ out,
                        int parity) {
    int i = blockIdx.x * blockDim.x + threadIdx.x;
    if (i >= 2 * N_NODES) return;
    out[i] = g_acc[i] + g_a[NLAYERS] * nxt_of(parity)[i] + b[i & 1];
}

// ---------------------------------------------------------------------------
extern "C" void kernel_launch(void* const* d_in, const int* in_sizes, int n_in,
                              void* d_out, int out_size) {
    const int*   node_idx = (const int*)  d_in[0];
    const int*   adj_row  = (const int*)  d_in[1];
    const int*   adj_col  = (const int*)  d_in[2];
    const float* adj_val  = (const float*)d_in[3];
    const float* emb      = (const float*)d_in[4];
    const float* alpha    = (const float*)d_in[5];
    const float* W        = (const float*)d_in[6];
    const float* b        = (const float*)d_in[7];
    float*       out      = (float*)d_out;

    k_softmax<<<1, 1>>>(alpha);

    {   // one warp per node
        int threads = 256;
        int blocks  = (N_NODES * 32 + threads - 1) / threads;
        k_init<<<blocks, threads>>>(node_idx, emb, W);
    }

    const int vecBlocks  = (2 * N_NODES + 255) / 256;
    const int edgeBlocks = (N_EDGES + 255) / 256;

    for (int layer = 0; layer < NLAYERS; layer++) {
        int p = layer & 1;   // p=0: cur=A, nxt=B ; p=1: cur=B, nxt=A
        k_zero<<<vecBlocks, 256>>>(p);
        k_scatter<<<edgeBlocks, 256>>>(adj_row, adj_col, adj_val, p);
        if (layer < NLAYERS - 1) {
            k_accum<<<vecBlocks, 256>>>(layer, p);
        } else {
            k_final<<<vecBlocks, 256>>>(b, out, p);
        }
    }
}

// round 2
// speedup vs baseline: 1.3713x; 1.3713x over previous
#include <cuda_runtime.h>

// LightGCN: out = sum_i a_i * A^i X W + b  ==  sum_i a_i * A^i (X W) + b
// Propagate in the 2-dim projected space instead of 128-dim embedding space.
// R2: v2.f32 vector atomics, edge-pair vector loads, fused zeroing.

#define N_NODES 100000
#define N_EDGES 1600000
#define DIM     128
#define NLAYERS 3

__device__ __align__(16) float g_a[NLAYERS + 1];
__device__ __align__(16) float g_bufA[2 * N_NODES];
__device__ __align__(16) float g_bufB[2 * N_NODES];
__device__ __align__(16) float g_acc [2 * N_NODES];

__device__ __forceinline__ const float* cur_of(int p) { return p ? g_bufB : g_bufA; }
__device__ __forceinline__ float*       curm_of(int p){ return p ? g_bufB : g_bufA; }
__device__ __forceinline__ float*       nxt_of(int p) { return p ? g_bufA : g_bufB; }

// one 8-byte vector RED instead of two scalar float atomics
__device__ __forceinline__ void red_add_v2(float* p, float a, float b) {
    asm volatile("red.global.add.v2.f32 [%0], {%1, %2};"
                 :: "l"(p), "f"(a), "f"(b) : "memory");
}

// ---------------------------------------------------------------------------
__global__ void k_softmax(const float* __restrict__ alpha) {
    float m = alpha[0];
    #pragma unroll
    for (int i = 1; i < NLAYERS + 1; i++) m = fmaxf(m, alpha[i]);
    float e[NLAYERS + 1], s = 0.f;
    #pragma unroll
    for (int i = 0; i < NLAYERS + 1; i++) { e[i] = expf(alpha[i] - m); s += e[i]; }
    #pragma unroll
    for (int i = 0; i < NLAYERS + 1; i++) g_a[i] = e[i] / s;
}

// ---------------------------------------------------------------------------
// Y = X W; bufA = Y; acc = a0 * Y; ALSO zero bufB (layer-0 scatter target).
__global__ void k_init(const int* __restrict__ node_idx,
                       const float* __restrict__ emb,
                       const float* __restrict__ W) {
    int gtid = blockIdx.x * blockDim.x + threadIdx.x;
    int warp = gtid >> 5;
    int lane = threadIdx.x & 31;
    if (warp >= N_NODES) return;

    // fused zeroing of bufB: first 2*N_NODES threads each clear one element
    if (gtid < 2 * N_NODES) g_bufB[gtid] = 0.f;

    int src = node_idx[warp];
    float4 v = reinterpret_cast<const float4*>(emb + (long long)src * DIM)[lane];
    const float4* w4 = reinterpret_cast<const float4*>(W + lane * 8);
    float4 w01 = w4[0];
    float4 w23 = w4[1];

    float s0 = v.x * w01.x + v.y * w01.z + v.z * w23.x + v.w * w23.z;
    float s1 = v.x * w01.y + v.y * w01.w + v.z * w23.y + v.w * w23.w;
    #pragma unroll
    for (int o = 16; o; o >>= 1) {
        s0 += __shfl_xor_sync(0xFFFFFFFFu, s0, o);
        s1 += __shfl_xor_sync(0xFFFFFFFFu, s1, o);
    }
    if (lane == 0) {
        float a0 = g_a[0];
        g_bufA[2 * warp + 0] = s0;
        g_bufA[2 * warp + 1] = s1;
        g_acc [2 * warp + 0] = a0 * s0;
        g_acc [2 * warp + 1] = a0 * s1;
    }
}

// ---------------------------------------------------------------------------
// edge-parallel SpMM in 2-dim space, 2 edges/thread, v2 vector REDs.
__global__ void k_scatter(const int2*   __restrict__ row2,
                          const int2*   __restrict__ col2,
                          const float2* __restrict__ val2,
                          int parity) {
    int i = blockIdx.x * blockDim.x + threadIdx.x;
    if (i >= N_EDGES / 2) return;
    int2   r = row2[i];
    int2   c = col2[i];
    float2 v = val2[i];
    const float2* cur = reinterpret_cast<const float2*>(cur_of(parity));
    float*        nxt = nxt_of(parity);
    float2 x0 = cur[c.x];
    float2 x1 = cur[c.y];
    red_add_v2(nxt + 2 * r.x, v.x * x0.x, v.x * x0.y);
    red_add_v2(nxt + 2 * r.y, v.y * x1.x, v.y * x1.y);
}

// ---------------------------------------------------------------------------
// acc += a[layer+1] * nxt ; zero cur (it becomes next layer's scatter target).
__global__ void k_accum(int layer, int parity) {
    int i = blockIdx.x * blockDim.x + threadIdx.x;
    if (i >= (2 * N_NODES) / 4) return;
    float4* acc = reinterpret_cast<float4*>(g_acc);
    const float4* nxt = reinterpret_cast<const float4*>(nxt_of(parity));
    float4* cur = reinterpret_cast<float4*>(curm_of(parity));
    float a = g_a[layer + 1];
    float4 s = acc[i], n = nxt[i];
    s.x += a * n.x; s.y += a * n.y; s.z += a * n.z; s.w += a * n.w;
    acc[i] = s;
    cur[i] = make_float4(0.f, 0.f, 0.f, 0.f);
}

// ---------------------------------------------------------------------------
// out = acc + a[3] * nxt + b
__global__ void k_final(const float* __restrict__ b, float* __restrict__ out,
                        int parity) {
    int i = blockIdx.x * blockDim.x + threadIdx.x;
    if (i >= (2 * N_NODES) / 4) return;
    const float4* acc = reinterpret_cast<const float4*>(g_acc);
    const float4* nxt = reinterpret_cast<const float4*>(nxt_of(parity));
    float a = g_a[NLAYERS];
    float b0 = b[0], b1 = b[1];
    float4 s = acc[i], n = nxt[i];
    float4 o;
    o.x = s.x + a * n.x + b0;
    o.y = s.y + a * n.y + b1;
    o.z = s.z + a * n.z + b0;
    o.w = s.w + a * n.w + b1;
    reinterpret_cast<float4*>(out)[i] = o;
}

// ---------------------------------------------------------------------------
extern "C" void kernel_launch(void* const* d_in, const int* in_sizes, int n_in,
                              void* d_out, int out_size) {
    const int*   node_idx = (const int*)  d_in[0];
    const int*   adj_row  = (const int*)  d_in[1];
    const int*   adj_col  = (const int*)  d_in[2];
    const float* adj_val  = (const float*)d_in[3];
    const float* emb      = (const float*)d_in[4];
    const float* alpha    = (const float*)d_in[5];
    const float* W        = (const float*)d_in[6];
    const float* b        = (const float*)d_in[7];
    float*       out      = (float*)d_out;

    k_softmax<<<1, 1>>>(alpha);

    {   // one warp per node (+ fused bufB zeroing)
        int threads = 256;
        int blocks  = (N_NODES * 32 + threads - 1) / threads;
        k_init<<<blocks, threads>>>(node_idx, emb, W);
    }

    const int vecBlocks  = ((2 * N_NODES) / 4 + 255) / 256;
    const int edgeBlocks = (N_EDGES / 2 + 255) / 256;

    const int2*   row2 = (const int2*)  adj_row;
    const int2*   col2 = (const int2*)  adj_col;
    const float2* val2 = (const float2*)adj_val;

    // layer 0: cur=A, nxt=B (B zeroed in k_init)
    k_scatter<<<edgeBlocks, 256>>>(row2, col2, val2, 0);
    k_accum  <<<vecBlocks, 256>>>(0, 0);     // acc += a1*B ; zero A
    // layer 1: cur=B, nxt=A
    k_scatter<<<edgeBlocks, 256>>>(row2, col2, val2, 1);
    k_accum  <<<vecBlocks, 256>>>(1, 1);     // acc += a2*A ; zero B
    // layer 2: cur=A, nxt=B
    k_scatter<<<edgeBlocks, 256>>>(row2, col2, val2, 0);
    k_final  <<<vecBlocks, 256>>>(b, out, 0);
}

// round 4
// speedup vs baseline: 1.4803x; 1.0795x over previous
#include <cuda_runtime.h>

// LightGCN: out = sum_i a_i * A^i X W + b  ==  sum_i a_i * A^i (X W) + b
// Propagate in 2-dim projected space. R4: per-power buffers, single fused
// epilogue, 4-edge vectorized scatter. Buffers resolved DEVICE-side via
// integer index (passing __device__ symbols from host tripped the
// allocation guard in R3).

#define N_NODES 100000
#define N_EDGES 1600000
#define DIM     128
#define NLAYERS 3

// buf[i] holds A^i (XW), 2 floats per node.
__device__ __align__(16) float g_buf0[2 * N_NODES];
__device__ __align__(16) float g_buf1[2 * N_NODES];
__device__ __align__(16) float g_buf2[2 * N_NODES];
__device__ __align__(16) float g_buf3[2 * N_NODES];

__device__ __forceinline__ float* buf_of(int i) {
    return i == 0 ? g_buf0 : i == 1 ? g_buf1 : i == 2 ? g_buf2 : g_buf3;
}

// one 8-byte vector RED instead of two scalar float atomics
__device__ __forceinline__ void red_add_v2(float* p, float a, float b) {
    asm volatile("red.global.add.v2.f32 [%0], {%1, %2};"
                 :: "l"(p), "f"(a), "f"(b) : "memory");
}

// ---------------------------------------------------------------------------
// buf0 = (embedding[node_idx]) @ W ; also zero buf1..buf3.
// One warp per node: lane l loads float4 at feature 4l (512B coalesced/warp).
__global__ void k_init(const int* __restrict__ node_idx,
                       const float* __restrict__ emb,
                       const float* __restrict__ W) {
    int gtid = blockIdx.x * blockDim.x + threadIdx.x;
    int warp = gtid >> 5;
    int lane = threadIdx.x & 31;
    if (warp >= N_NODES) return;

    // fused zeroing of the three scatter targets
    if (gtid < 2 * N_NODES) {
        g_buf1[gtid] = 0.f;
        g_buf2[gtid] = 0.f;
        g_buf3[gtid] = 0.f;
    }

    int src = node_idx[warp];
    float4 v = reinterpret_cast<const float4*>(emb + (long long)src * DIM)[lane];
    const float4* w4 = reinterpret_cast<const float4*>(W + lane * 8);
    float4 w01 = w4[0];   // k0c0 k0c1 k1c0 k1c1
    float4 w23 = w4[1];   // k2c0 k2c1 k3c0 k3c1

    float s0 = v.x * w01.x + v.y * w01.z + v.z * w23.x + v.w * w23.z;
    float s1 = v.x * w01.y + v.y * w01.w + v.z * w23.y + v.w * w23.w;
    #pragma unroll
    for (int o = 16; o; o >>= 1) {
        s0 += __shfl_xor_sync(0xFFFFFFFFu, s0, o);
        s1 += __shfl_xor_sync(0xFFFFFFFFu, s1, o);
    }
    if (lane == 0) {
        g_buf0[2 * warp + 0] = s0;
        g_buf0[2 * warp + 1] = s1;
    }
}

// ---------------------------------------------------------------------------
// edge-parallel SpMM in 2-dim space: buf[d][r] += val * buf[s][c],
// 4 edges/thread; buffers chosen device-side by index.
__global__ void k_scatter(const int4*   __restrict__ row4,
                          const int4*   __restrict__ col4,
                          const float4* __restrict__ val4,
                          int sIdx, int dIdx) {
    int i = blockIdx.x * blockDim.x + threadIdx.x;
    if (i >= N_EDGES / 4) return;
    int4   r = row4[i];
    int4   c = col4[i];
    float4 v = val4[i];
    const float2* cur = reinterpret_cast<const float2*>(buf_of(sIdx));
    float*        dst = buf_of(dIdx);
    float2 x0 = cur[c.x];
    float2 x1 = cur[c.y];
    float2 x2 = cur[c.z];
    float2 x3 = cur[c.w];
    red_add_v2(dst + 2 * r.x, v.x * x0.x, v.x * x0.y);
    red_add_v2(dst + 2 * r.y, v.y * x1.x, v.y * x1.y);
    red_add_v2(dst + 2 * r.z, v.z * x2.x, v.z * x2.y);
    red_add_v2(dst + 2 * r.w, v.w * x3.x, v.w * x3.y);
}

// ---------------------------------------------------------------------------
// out = a0*buf0 + a1*buf1 + a2*buf2 + a3*buf3 + b, a = softmax(alpha).
__global__ void k_final(const float* __restrict__ alpha,
                        const float* __restrict__ b,
                        float* __restrict__ out) {
    int i = blockIdx.x * blockDim.x + threadIdx.x;
    if (i >= (2 * N_NODES) / 4) return;

    // softmax over 4 scalars, recomputed per thread (L1-resident, trivial)
    float al0 = alpha[0], al1 = alpha[1], al2 = alpha[2], al3 = alpha[3];
    float m = fmaxf(fmaxf(al0, al1), fmaxf(al2, al3));
    float e0 = expf(al0 - m), e1 = expf(al1 - m),
          e2 = expf(al2 - m), e3 = expf(al3 - m);
    float inv = 1.f / (e0 + e1 + e2 + e3);
    float a0 = e0 * inv, a1 = e1 * inv, a2 = e2 * inv, a3 = e3 * inv;

    float4 p0 = reinterpret_cast<const float4*>(g_buf0)[i];
    float4 p1 = reinterpret_cast<const float4*>(g_buf1)[i];
    float4 p2 = reinterpret_cast<const float4*>(g_buf2)[i];
    float4 p3 = reinterpret_cast<const float4*>(g_buf3)[i];
    float b0 = b[0], b1 = b[1];

    float4 o;
    o.x = a0 * p0.x + a1 * p1.x + a2 * p2.x + a3 * p3.x + b0;
    o.y = a0 * p0.y + a1 * p1.y + a2 * p2.y + a3 * p3.y + b1;
    o.z = a0 * p0.z + a1 * p1.z + a2 * p2.z + a3 * p3.z + b0;
    o.w = a0 * p0.w + a1 * p1.w + a2 * p2.w + a3 * p3.w + b1;
    reinterpret_cast<float4*>(out)[i] = o;
}

// ---------------------------------------------------------------------------
extern "C" void kernel_launch(void* const* d_in, const int* in_sizes, int n_in,
                              void* d_out, int out_size) {
    const int*   node_idx = (const int*)  d_in[0];
    const int*   adj_row  = (const int*)  d_in[1];
    const int*   adj_col  = (const int*)  d_in[2];
    const float* adj_val  = (const float*)d_in[3];
    const float* emb      = (const float*)d_in[4];
    const float* alpha    = (const float*)d_in[5];
    const float* W        = (const float*)d_in[6];
    const float* b        = (const float*)d_in[7];
    float*       out      = (float*)d_out;

    {   // one warp per node (+ fused zeroing of buf1..buf3)
        int threads = 256;
        int blocks  = (N_NODES * 32 + threads - 1) / threads;
        k_init<<<blocks, threads>>>(node_idx, emb, W);
    }

    const int edgeBlocks = (N_EDGES / 4 + 255) / 256;
    const int4*   row4 = (const int4*)  adj_row;
    const int4*   col4 = (const int4*)  adj_col;
    const float4* val4 = (const float4*)adj_val;

    k_scatter<<<edgeBlocks, 256>>>(row4, col4, val4, 0, 1);
    k_scatter<<<edgeBlocks, 256>>>(row4, col4, val4, 1, 2);
    k_scatter<<<edgeBlocks, 256>>>(row4, col4, val4, 2, 3);

    const int vecBlocks = ((2 * N_NODES) / 4 + 255) / 256;
    k_final<<<vecBlocks, 256>>>(alpha, b, out);
}